// round 1
// baseline (speedup 1.0000x reference)
#include <cuda_runtime.h>
#include <math.h>

#define NNODE 50000
#define NEDGE 400000

// ---------------- device scratch (no allocation allowed) ----------------
__device__ float g_acc1[(size_t)NNODE * 128];  // spmm1 accumulator
__device__ float g_x2[(size_t)NNODE * 64];     // x@W2 result (later reused as h1)
__device__ float g_acc2[(size_t)NNODE * 64];   // spmm2 accumulator
__device__ float g_h[(size_t)NNODE * 64];      // GRU hidden
__device__ float g_gi[(size_t)NNODE * 192];    // GRU input gates
__device__ float g_gh[(size_t)NNODE * 192];    // GRU hidden gates
__device__ float g_z[(size_t)NNODE * 128];     // [emb | neigh]
__device__ float g_deg[NNODE];
__device__ float g_stats[128];                 // [sum(64) | sumsq(64)]
__device__ float g_wih_t[64 * 192];            // w_ih transposed to [K,M]
__device__ float g_whh_t[64 * 192];

__device__ __forceinline__ float sigmoidf_(float x) { return 1.0f / (1.0f + expf(-x)); }

// ---------------- utility kernels ----------------
__global__ void zero_kernel(float* __restrict__ p, int n) {
    int i = blockIdx.x * blockDim.x + threadIdx.x;
    if (i < n) p[i] = 0.0f;
}

// in: [192,64] row-major -> out: [64,192] row-major
__global__ void transpose_w_kernel(const float* __restrict__ in, float* __restrict__ out) {
    int idx = blockIdx.x * blockDim.x + threadIdx.x;
    if (idx < 192 * 64) {
        int m = idx >> 6;
        int k = idx & 63;
        out[k * 192 + m] = in[idx];
    }
}

// ---------------- SpMM scatter kernels ----------------
// acc1[r,:] += v * W1[c,:]   (128 cols, 32 lanes x float4 per edge)
__global__ void spmm1_kernel(const int* __restrict__ adj_idx, const float* __restrict__ adj_val,
                             const int* __restrict__ start_day, int t,
                             const float* __restrict__ W1) {
    int gid = blockIdx.x * 256 + threadIdx.x;
    int e = gid >> 5;
    if (e >= NEDGE) return;
    int lane = gid & 31;
    int day = *start_day + t;
    const int* rowp = adj_idx + (size_t)day * 2 * NEDGE;
    int r = rowp[e];
    int c = rowp[NEDGE + e];
    float v = adj_val[(size_t)day * NEDGE + e];
    float4 w = *reinterpret_cast<const float4*>(W1 + (size_t)c * 128 + lane * 4);
    float* dst = g_acc1 + (size_t)r * 128 + lane * 4;
    atomicAdd(dst + 0, v * w.x);
    atomicAdd(dst + 1, v * w.y);
    atomicAdd(dst + 2, v * w.z);
    atomicAdd(dst + 3, v * w.w);
}

// acc2[r,:] += v * x2[c,:]   (64 cols, 16 lanes x float4 per edge)
__global__ void spmm2_kernel(const int* __restrict__ adj_idx, const float* __restrict__ adj_val,
                             const int* __restrict__ start_day, int t) {
    int gid = blockIdx.x * 256 + threadIdx.x;
    int e = gid >> 4;
    if (e >= NEDGE) return;
    int lane = gid & 15;
    int day = *start_day + t;
    const int* rowp = adj_idx + (size_t)day * 2 * NEDGE;
    int r = rowp[e];
    int c = rowp[NEDGE + e];
    float v = adj_val[(size_t)day * NEDGE + e];
    float4 w = *reinterpret_cast<const float4*>(g_x2 + (size_t)c * 64 + lane * 4);
    float* dst = g_acc2 + (size_t)r * 64 + lane * 4;
    atomicAdd(dst + 0, v * w.x);
    atomicAdd(dst + 1, v * w.y);
    atomicAdd(dst + 2, v * w.z);
    atomicAdd(dst + 3, v * w.w);
}

// ---------------- tiled GEMM: C[N,Mtot] = f(A[N,K]) @ B[K,Mtot] (+obias)(relu) --------
// ATRANS: 0 = A as-is, 1 = A + abias[k], 2 = relu(A + abias[k])
// B is k-major [K, Mtot] row-major.
// Block tile 64 rows x 64 cols, 256 threads, 4x4 micro-tile, K chunked at 64.
template <int K, int ATRANS, bool OUTBIAS, bool OUTRELU>
__global__ void gemm_kernel(const float* __restrict__ A, const float* __restrict__ abias,
                            const float* __restrict__ B, const float* __restrict__ obias,
                            float* __restrict__ C, int Mtot) {
    __shared__ float As[64 * 68];  // row-major [row][k], stride 68 (pad)
    __shared__ float Bs[64 * 64];  // [k][m]
    const int tid = threadIdx.x;
    const int node0 = blockIdx.x * 64;
    const int col0 = blockIdx.y * 64;
    const int tx = tid & 15;
    const int ty = tid >> 4;

    float acc[4][4];
#pragma unroll
    for (int i = 0; i < 4; i++)
#pragma unroll
        for (int j = 0; j < 4; j++) acc[i][j] = 0.0f;

    for (int kc = 0; kc < K; kc += 64) {
        // --- load A chunk (64 rows x 64 k), apply ATRANS ---
        for (int idx = tid; idx < 64 * 16; idx += 256) {
            int row = idx >> 4;
            int kk = (idx & 15) << 2;
            int node = node0 + row;
            float4 a = make_float4(0.f, 0.f, 0.f, 0.f);
            if (node < NNODE) a = *reinterpret_cast<const float4*>(A + (size_t)node * K + kc + kk);
            if (ATRANS >= 1) {
                a.x += abias[kc + kk + 0];
                a.y += abias[kc + kk + 1];
                a.z += abias[kc + kk + 2];
                a.w += abias[kc + kk + 3];
                if (ATRANS == 2) {
                    a.x = fmaxf(a.x, 0.f); a.y = fmaxf(a.y, 0.f);
                    a.z = fmaxf(a.z, 0.f); a.w = fmaxf(a.w, 0.f);
                }
            }
            As[row * 68 + kk + 0] = a.x;
            As[row * 68 + kk + 1] = a.y;
            As[row * 68 + kk + 2] = a.z;
            As[row * 68 + kk + 3] = a.w;
        }
        // --- load B chunk (64 k x 64 m), coalesced & conflict-free ---
        for (int idx = tid; idx < 64 * 16; idx += 256) {
            int k = idx >> 4;
            int mm = (idx & 15) << 2;
            float4 b = *reinterpret_cast<const float4*>(B + (size_t)(kc + k) * Mtot + col0 + mm);
            *reinterpret_cast<float4*>(&Bs[k * 64 + mm]) = b;
        }
        __syncthreads();

#pragma unroll 8
        for (int k = 0; k < 64; k++) {
            float4 b = *reinterpret_cast<const float4*>(&Bs[k * 64 + tx * 4]);
            float a0 = As[(ty * 4 + 0) * 68 + k];
            float a1 = As[(ty * 4 + 1) * 68 + k];
            float a2 = As[(ty * 4 + 2) * 68 + k];
            float a3 = As[(ty * 4 + 3) * 68 + k];
            acc[0][0] += a0 * b.x; acc[0][1] += a0 * b.y; acc[0][2] += a0 * b.z; acc[0][3] += a0 * b.w;
            acc[1][0] += a1 * b.x; acc[1][1] += a1 * b.y; acc[1][2] += a1 * b.z; acc[1][3] += a1 * b.w;
            acc[2][0] += a2 * b.x; acc[2][1] += a2 * b.y; acc[2][2] += a2 * b.z; acc[2][3] += a2 * b.w;
            acc[3][0] += a3 * b.x; acc[3][1] += a3 * b.y; acc[3][2] += a3 * b.z; acc[3][3] += a3 * b.w;
        }
        __syncthreads();
    }

#pragma unroll
    for (int i = 0; i < 4; i++) {
        int node = node0 + ty * 4 + i;
        if (node < NNODE) {
            float4 o;
            o.x = acc[i][0]; o.y = acc[i][1]; o.z = acc[i][2]; o.w = acc[i][3];
            if (OUTBIAS) {
                o.x += obias[col0 + tx * 4 + 0];
                o.y += obias[col0 + tx * 4 + 1];
                o.z += obias[col0 + tx * 4 + 2];
                o.w += obias[col0 + tx * 4 + 3];
            }
            if (OUTRELU) {
                o.x = fmaxf(o.x, 0.f); o.y = fmaxf(o.y, 0.f);
                o.z = fmaxf(o.z, 0.f); o.w = fmaxf(o.w, 0.f);
            }
            *reinterpret_cast<float4*>(C + (size_t)node * Mtot + col0 + tx * 4) = o;
        }
    }
}

// ---------------- GRU gate fuse ----------------
__global__ void gru_gate_kernel() {
    int idx = blockIdx.x * 256 + threadIdx.x;
    if (idx >= NNODE * 64) return;
    int n = idx >> 6;
    int j = idx & 63;
    const float* gi = g_gi + (size_t)n * 192;
    const float* gh = g_gh + (size_t)n * 192;
    float ir = gi[j], iz = gi[64 + j], in_ = gi[128 + j];
    float hr = gh[j], hz = gh[64 + j], hn = gh[128 + j];
    float r = sigmoidf_(ir + hr);
    float z = sigmoidf_(iz + hz);
    float nn = tanhf(in_ + r * hn);
    float hp = g_h[idx];
    g_h[idx] = (1.0f - z) * nn + z * hp;
}

// ---------------- batch norm ----------------
__global__ void bn_stats_kernel() {
    int col = threadIdx.x & 63;
    int rep = threadIdx.x >> 6;  // 0..3
    float s = 0.f, s2 = 0.f;
    for (int r = blockIdx.x * 4 + rep; r < NNODE; r += gridDim.x * 4) {
        float v = g_h[(size_t)r * 64 + col];
        s += v;
        s2 += v * v;
    }
    __shared__ float ss[4][64];
    __shared__ float ss2[4][64];
    ss[rep][col] = s;
    ss2[rep][col] = s2;
    __syncthreads();
    if (rep == 0) {
        s = ss[0][col] + ss[1][col] + ss[2][col] + ss[3][col];
        s2 = ss2[0][col] + ss2[1][col] + ss2[2][col] + ss2[3][col];
        atomicAdd(&g_stats[col], s);
        atomicAdd(&g_stats[64 + col], s2);
    }
}

__global__ void bn_norm_kernel(const float* __restrict__ gamma, const float* __restrict__ beta) {
    int idx = blockIdx.x * 256 + threadIdx.x;
    if (idx >= NNODE * 64) return;
    int n = idx >> 6;
    int col = idx & 63;
    float mean = g_stats[col] * (1.0f / NNODE);
    float var = g_stats[64 + col] * (1.0f / NNODE) - mean * mean;
    float inv = rsqrtf(var + 1e-5f);
    float v = (g_h[idx] - mean) * inv * gamma[col] + beta[col];
    g_z[(size_t)n * 128 + col] = v;  // lower half of z = normalized emb
}

// ---------------- attention on day end_day+1 ----------------
__global__ void deg_kernel(const int* __restrict__ adj_idx, const int* __restrict__ end_day) {
    int e = blockIdx.x * 256 + threadIdx.x;
    if (e >= NEDGE) return;
    int day = *end_day + 1;
    const int* rowp = adj_idx + (size_t)day * 2 * NEDGE;
    int r = rowp[e];
    int c = rowp[NEDGE + e];
    if (r != c) atomicAdd(&g_deg[r], 1.0f);
}

__global__ void attn_kernel(const int* __restrict__ adj_idx, const int* __restrict__ end_day,
                            const float* __restrict__ aw, const float* __restrict__ ab) {
    int gid = blockIdx.x * 256 + threadIdx.x;
    int e = gid >> 5;
    if (e >= NEDGE) return;
    int lane = gid & 31;
    int day = *end_day + 1;
    const int* rowp = adj_idx + (size_t)day * 2 * NEDGE;
    int r = rowp[e];
    int c = rowp[NEDGE + e];
    if (r == c) return;
    const float* zr = g_z + (size_t)r * 128;
    const float* zc = g_z + (size_t)c * 128;
    float ec0 = zc[lane];
    float ec1 = zc[lane + 32];
    float p = zr[lane] * aw[lane] + zr[lane + 32] * aw[lane + 32] +
              ec0 * aw[64 + lane] + ec1 * aw[96 + lane];
#pragma unroll
    for (int o = 16; o > 0; o >>= 1) p += __shfl_xor_sync(0xffffffffu, p, o);
    float w = sigmoidf_(p + ab[0]);
    float d = g_deg[r];
    float invd = (d != 0.0f) ? (1.0f / d) : 1.0f;
    float ev = invd * w;
    atomicAdd(&g_z[(size_t)r * 128 + 64 + lane], ev * ec0);
    atomicAdd(&g_z[(size_t)r * 128 + 96 + lane], ev * ec1);
}

// ---------------- final logits + log_softmax ----------------
__global__ void logits_kernel(const float* __restrict__ w2, const float* __restrict__ b2,
                              float* __restrict__ out) {
    int gid = blockIdx.x * 256 + threadIdx.x;
    int n = gid >> 5;
    if (n >= NNODE) return;
    int lane = gid & 31;
    float v0 = g_x2[(size_t)n * 64 + lane];        // g_x2 holds h1 here
    float v1 = g_x2[(size_t)n * 64 + 32 + lane];
    float l0 = v0 * w2[lane * 2 + 0] + v1 * w2[(lane + 32) * 2 + 0];
    float l1 = v0 * w2[lane * 2 + 1] + v1 * w2[(lane + 32) * 2 + 1];
#pragma unroll
    for (int o = 16; o > 0; o >>= 1) {
        l0 += __shfl_down_sync(0xffffffffu, l0, o);
        l1 += __shfl_down_sync(0xffffffffu, l1, o);
    }
    if (lane == 0) {
        l0 += b2[0];
        l1 += b2[1];
        float m = fmaxf(l0, l1);
        float lse = m + logf(expf(l0 - m) + expf(l1 - m));
        out[(size_t)n * 2 + 0] = l0 - lse;
        out[(size_t)n * 2 + 1] = l1 - lse;
    }
}

// ---------------- host launch ----------------
extern "C" void kernel_launch(void* const* d_in, const int* in_sizes, int n_in,
                              void* d_out, int out_size) {
    const int* adj_idx = (const int*)d_in[0];
    const float* adj_val = (const float*)d_in[1];
    const int* p_start = (const int*)d_in[2];
    const int* p_end = (const int*)d_in[3];
    const float* W1 = (const float*)d_in[4];
    const float* b1 = (const float*)d_in[5];
    const float* W2 = (const float*)d_in[6];
    const float* b2 = (const float*)d_in[7];
    const float* w_ih = (const float*)d_in[8];
    const float* w_hh = (const float*)d_in[9];
    const float* b_ih = (const float*)d_in[10];
    const float* b_hh = (const float*)d_in[11];
    const float* bn_gamma = (const float*)d_in[12];
    const float* bn_beta = (const float*)d_in[13];
    const float* attn_w = (const float*)d_in[14];
    const float* attn_b = (const float*)d_in[15];
    const float* np_w1 = (const float*)d_in[16];
    const float* np_b1 = (const float*)d_in[17];
    const float* np_w2 = (const float*)d_in[18];
    const float* np_b2 = (const float*)d_in[19];
    float* out = (float*)d_out;

    float *acc1, *x2, *acc2, *h, *gi, *gh, *z, *deg, *stats, *wih_t, *whh_t;
    cudaGetSymbolAddress((void**)&acc1, g_acc1);
    cudaGetSymbolAddress((void**)&x2, g_x2);
    cudaGetSymbolAddress((void**)&acc2, g_acc2);
    cudaGetSymbolAddress((void**)&h, g_h);
    cudaGetSymbolAddress((void**)&gi, g_gi);
    cudaGetSymbolAddress((void**)&gh, g_gh);
    cudaGetSymbolAddress((void**)&z, g_z);
    cudaGetSymbolAddress((void**)&deg, g_deg);
    cudaGetSymbolAddress((void**)&stats, g_stats);
    cudaGetSymbolAddress((void**)&wih_t, g_wih_t);
    cudaGetSymbolAddress((void**)&whh_t, g_whh_t);

    const int nGemmBlocks = (NNODE + 63) / 64;  // 782

    // one-time per launch prep
    transpose_w_kernel<<<(192 * 64 + 255) / 256, 256>>>(w_ih, wih_t);
    transpose_w_kernel<<<(192 * 64 + 255) / 256, 256>>>(w_hh, whh_t);
    zero_kernel<<<(NNODE * 64 + 255) / 256, 256>>>(h, NNODE * 64);
    zero_kernel<<<(NNODE * 128 + 255) / 256, 256>>>(z, NNODE * 128);
    zero_kernel<<<(NNODE + 255) / 256, 256>>>(deg, NNODE);
    zero_kernel<<<1, 128>>>(stats, 128);

    for (int t = 0; t < 7; t++) {
        zero_kernel<<<(NNODE * 128 + 255) / 256, 256>>>(acc1, NNODE * 128);
        spmm1_kernel<<<(NEDGE * 32 + 255) / 256, 256>>>(adj_idx, adj_val, p_start, t, W1);
        // x2 = relu(acc1 + b1) @ W2
        gemm_kernel<128, 2, false, false>
            <<<dim3(nGemmBlocks, 1), 256>>>(acc1, b1, W2, nullptr, x2, 64);
        zero_kernel<<<(NNODE * 64 + 255) / 256, 256>>>(acc2, NNODE * 64);
        spmm2_kernel<<<(NEDGE * 16 + 255) / 256, 256>>>(adj_idx, adj_val, p_start, t);
        // gi = (acc2 + b2) @ w_ih^T + b_ih
        gemm_kernel<64, 1, true, false>
            <<<dim3(nGemmBlocks, 3), 256>>>(acc2, b2, wih_t, b_ih, gi, 192);
        // gh = h @ w_hh^T + b_hh
        gemm_kernel<64, 0, true, false>
            <<<dim3(nGemmBlocks, 3), 256>>>(h, nullptr, whh_t, b_hh, gh, 192);
        gru_gate_kernel<<<(NNODE * 64 + 255) / 256, 256>>>();
    }

    // batch norm -> z[:, 0:64]
    bn_stats_kernel<<<128, 256>>>();
    bn_norm_kernel<<<(NNODE * 64 + 255) / 256, 256>>>(bn_gamma, bn_beta);

    // attention on day end_day+1 -> z[:, 64:128]
    deg_kernel<<<(NEDGE + 255) / 256, 256>>>(adj_idx, p_end);
    attn_kernel<<<(NEDGE * 32 + 255) / 256, 256>>>(adj_idx, p_end, attn_w, attn_b);

    // h1 = relu(z @ np_w1 + np_b1)  (stored in g_x2)
    gemm_kernel<128, 0, true, true>
        <<<dim3(nGemmBlocks, 1), 256>>>(z, nullptr, np_w1, np_b1, x2, 64);

    // pred = log_softmax(h1 @ np_w2 + np_b2)
    logits_kernel<<<(NNODE * 32 + 255) / 256, 256>>>(np_w2, np_b2, out);
}

// round 2
// speedup vs baseline: 1.5855x; 1.5855x over previous
#include <cuda_runtime.h>
#include <math.h>

#define NNODE 50000
#define NEDGE 400000
#define SDAYS 8
#define BPD 98  // ceil(NNODE/512)

// ---------------- device scratch (no allocation allowed) ----------------
__device__ __align__(16) float g_x2[(size_t)NNODE * 64];   // x@W2 result (later reused as h1)
__device__ __align__(16) float g_h[(size_t)NNODE * 64];    // GRU hidden
__device__ __align__(16) float g_gi[(size_t)NNODE * 192];  // GRU input gates
__device__ __align__(16) float g_gh[(size_t)NNODE * 192];  // GRU hidden gates
__device__ __align__(16) float g_z[(size_t)NNODE * 128];   // [emb | neigh]
__device__ float g_deg[NNODE];
__device__ float g_stats[128];                             // [sum(64) | sumsq(64)]
__device__ __align__(16) float g_wih_t[64 * 192];          // w_ih transposed to [K,M]
__device__ __align__(16) float g_whh_t[64 * 192];

// CSR structures (all 8 days)
__device__ int g_cnt[SDAYS * NNODE];
__device__ int g_scan[SDAYS * NNODE];
__device__ int g_part[SDAYS * BPD];
__device__ int g_rowptr[SDAYS * (NNODE + 1)];
__device__ int g_cursor[SDAYS * NNODE];
__device__ int g_ecol[(size_t)SDAYS * NEDGE];
__device__ __align__(16) float g_eval[(size_t)SDAYS * NEDGE];

__device__ __forceinline__ float sigmoidf_(float x) { return 1.0f / (1.0f + expf(-x)); }

// ---------------- utility kernels ----------------
__global__ void zero_f_kernel(float* __restrict__ p, int n) {
    int i = blockIdx.x * blockDim.x + threadIdx.x;
    if (i < n) p[i] = 0.0f;
}
__global__ void zero_i_kernel(int* __restrict__ p, int n) {
    int i = blockIdx.x * blockDim.x + threadIdx.x;
    if (i < n) p[i] = 0;
}

// in: [192,64] row-major -> out: [64,192] row-major
__global__ void transpose_w_kernel(const float* __restrict__ in, float* __restrict__ out) {
    int idx = blockIdx.x * blockDim.x + threadIdx.x;
    if (idx < 192 * 64) {
        int m = idx >> 6;
        int k = idx & 63;
        out[k * 192 + m] = in[idx];
    }
}

// ---------------- CSR build (all 8 days, once per launch) ----------------
__global__ void csr_count_kernel(const int* __restrict__ adj_idx) {
    int idx = blockIdx.x * 256 + threadIdx.x;
    if (idx >= SDAYS * NEDGE) return;
    int d = idx / NEDGE;
    int e = idx - d * NEDGE;
    int r = adj_idx[(size_t)d * 2 * NEDGE + e];
    atomicAdd(&g_cnt[d * NNODE + r], 1);
}

// Blelloch exclusive scan of 512 elements per block; block totals -> g_part
__global__ void csr_scan_block_kernel() {
    __shared__ int s[512];
    int d = blockIdx.y;
    int base = blockIdx.x * 512;
    int t = threadIdx.x;
    int i0 = base + t, i1 = base + t + 256;
    s[t] = (i0 < NNODE) ? g_cnt[d * NNODE + i0] : 0;
    s[t + 256] = (i1 < NNODE) ? g_cnt[d * NNODE + i1] : 0;
    int offset = 1;
    for (int n = 256; n > 0; n >>= 1) {
        __syncthreads();
        if (t < n) {
            int ai = offset * (2 * t + 1) - 1;
            int bi = offset * (2 * t + 2) - 1;
            s[bi] += s[ai];
        }
        offset <<= 1;
    }
    if (t == 0) {
        g_part[d * BPD + blockIdx.x] = s[511];
        s[511] = 0;
    }
    for (int n = 1; n < 512; n <<= 1) {
        offset >>= 1;
        __syncthreads();
        if (t < n) {
            int ai = offset * (2 * t + 1) - 1;
            int bi = offset * (2 * t + 2) - 1;
            int tv = s[ai];
            s[ai] = s[bi];
            s[bi] += tv;
        }
    }
    __syncthreads();
    if (i0 < NNODE) g_scan[d * NNODE + i0] = s[t];
    if (i1 < NNODE) g_scan[d * NNODE + i1] = s[t + 256];
}

// exclusive scan of per-block partials (<=128 per day), one block per day
__global__ void csr_scan_part_kernel() {
    __shared__ int s[128];
    int d = blockIdx.x, t = threadIdx.x;
    int v = (t < BPD) ? g_part[d * BPD + t] : 0;
    s[t] = v;
    __syncthreads();
    for (int off = 1; off < 128; off <<= 1) {
        int u = (t >= off) ? s[t - off] : 0;
        __syncthreads();
        s[t] += u;
        __syncthreads();
    }
    if (t < BPD) g_part[d * BPD + t] = s[t] - v;  // exclusive
}

__global__ void csr_apply_kernel() {
    int idx = blockIdx.x * 256 + threadIdx.x;
    if (idx >= SDAYS * NNODE) return;
    int d = idx / NNODE;
    int i = idx - d * NNODE;
    int v = g_scan[d * NNODE + i] + g_part[d * BPD + (i >> 9)];
    g_rowptr[d * (NNODE + 1) + i] = v;
    g_cursor[d * NNODE + i] = v;
    if (i == 0) g_rowptr[d * (NNODE + 1) + NNODE] = NEDGE;
}

__global__ void csr_scatter_kernel(const int* __restrict__ adj_idx, const float* __restrict__ adj_val) {
    int idx = blockIdx.x * 256 + threadIdx.x;
    if (idx >= SDAYS * NEDGE) return;
    int d = idx / NEDGE;
    int e = idx - d * NEDGE;
    const int* base = adj_idx + (size_t)d * 2 * NEDGE;
    int r = base[e];
    int c = base[NEDGE + e];
    float v = adj_val[(size_t)d * NEDGE + e];
    int pos = atomicAdd(&g_cursor[d * NNODE + r], 1);
    g_ecol[(size_t)d * NEDGE + pos] = c;
    g_eval[(size_t)d * NEDGE + pos] = v;
}

// ---------------- CSR gather helper: 2 features per lane ----------------
__device__ __forceinline__ float2 gather_row64(const int* __restrict__ ecol,
                                               const float* __restrict__ eval,
                                               int p0, int p1,
                                               const float* __restrict__ src, int ld, int off) {
    float ax = 0.f, ay = 0.f;
    int p = p0;
    for (; p + 2 <= p1; p += 2) {
        int c0 = ecol[p];
        int c1 = ecol[p + 1];
        float v0 = eval[p];
        float v1 = eval[p + 1];
        float2 w0 = *reinterpret_cast<const float2*>(src + (size_t)c0 * ld + off);
        float2 w1 = *reinterpret_cast<const float2*>(src + (size_t)c1 * ld + off);
        ax = fmaf(v0, w0.x, ax);
        ay = fmaf(v0, w0.y, ay);
        ax = fmaf(v1, w1.x, ax);
        ay = fmaf(v1, w1.y, ay);
    }
    if (p < p1) {
        int c0 = ecol[p];
        float v0 = eval[p];
        float2 w0 = *reinterpret_cast<const float2*>(src + (size_t)c0 * ld + off);
        ax = fmaf(v0, w0.x, ax);
        ay = fmaf(v0, w0.y, ay);
    }
    return make_float2(ax, ay);
}

// ---------------- fused: x2 = relu(spmm(W1)+b1) @ W2 ----------------
// block: 64 nodes x 64 cols, 256 threads, K=128 in two gathered chunks.
__global__ void gcn1_kernel(const int* __restrict__ p_start, int t,
                            const float* __restrict__ W1, const float* __restrict__ b1,
                            const float* __restrict__ W2) {
    __shared__ float As[64 * 68];
    __shared__ float Bs[64 * 64];
    int day = *p_start + t;
    const int* rowptr = g_rowptr + (size_t)day * (NNODE + 1);
    const int* ecol = g_ecol + (size_t)day * NEDGE;
    const float* eval = g_eval + (size_t)day * NEDGE;
    int tid = threadIdx.x, lane = tid & 31, wid = tid >> 5;
    int tx = tid & 15, ty = tid >> 4;
    int node0 = blockIdx.x * 64;

    float acc[4][4];
#pragma unroll
    for (int i = 0; i < 4; i++)
#pragma unroll
        for (int j = 0; j < 4; j++) acc[i][j] = 0.0f;

    for (int kc = 0; kc < 128; kc += 64) {
        if (kc) __syncthreads();
        // gather A chunk: warp w handles rows w*8..w*8+7; lane handles 2 features
#pragma unroll
        for (int rr = 0; rr < 8; rr++) {
            int row = wid * 8 + rr;
            int node = node0 + row;
            float2 a = make_float2(0.f, 0.f);
            if (node < NNODE) {
                a = gather_row64(ecol, eval, rowptr[node], rowptr[node + 1], W1, 128, kc + lane * 2);
                float2 bb = *reinterpret_cast<const float2*>(b1 + kc + lane * 2);
                a.x = fmaxf(a.x + bb.x, 0.f);
                a.y = fmaxf(a.y + bb.y, 0.f);
            }
            As[row * 68 + lane * 2] = a.x;
            As[row * 68 + lane * 2 + 1] = a.y;
        }
        for (int idx = tid; idx < 64 * 16; idx += 256) {
            int k = idx >> 4, mm = (idx & 15) << 2;
            *reinterpret_cast<float4*>(&Bs[k * 64 + mm]) =
                *reinterpret_cast<const float4*>(W2 + (size_t)(kc + k) * 64 + mm);
        }
        __syncthreads();
#pragma unroll 8
        for (int k = 0; k < 64; k++) {
            float4 b = *reinterpret_cast<const float4*>(&Bs[k * 64 + tx * 4]);
            float a0 = As[(ty * 4 + 0) * 68 + k];
            float a1 = As[(ty * 4 + 1) * 68 + k];
            float a2 = As[(ty * 4 + 2) * 68 + k];
            float a3 = As[(ty * 4 + 3) * 68 + k];
            acc[0][0] += a0 * b.x; acc[0][1] += a0 * b.y; acc[0][2] += a0 * b.z; acc[0][3] += a0 * b.w;
            acc[1][0] += a1 * b.x; acc[1][1] += a1 * b.y; acc[1][2] += a1 * b.z; acc[1][3] += a1 * b.w;
            acc[2][0] += a2 * b.x; acc[2][1] += a2 * b.y; acc[2][2] += a2 * b.z; acc[2][3] += a2 * b.w;
            acc[3][0] += a3 * b.x; acc[3][1] += a3 * b.y; acc[3][2] += a3 * b.z; acc[3][3] += a3 * b.w;
        }
    }
#pragma unroll
    for (int i = 0; i < 4; i++) {
        int node = node0 + ty * 4 + i;
        if (node < NNODE) {
            float4 o;
            o.x = acc[i][0]; o.y = acc[i][1]; o.z = acc[i][2]; o.w = acc[i][3];
            *reinterpret_cast<float4*>(g_x2 + (size_t)node * 64 + tx * 4) = o;
        }
    }
}

// ---------------- GRU GEMM: out[node,192] = A @ Bt + obias ----------------
// GATHER: A row = spmm(x2)[node] + abias  (CSR gather); else A = Asrc[node] direct.
// K=64, three 64-col output chunks computed in-kernel (A gathered once).
template <bool GATHER>
__global__ void gru_gemm_kernel(const int* __restrict__ p_start, int t,
                                const float* __restrict__ Asrc, const float* __restrict__ abias,
                                const float* __restrict__ Bt, const float* __restrict__ obias,
                                float* __restrict__ out) {
    __shared__ float As[64 * 68];
    __shared__ float Bs[64 * 64];
    int tid = threadIdx.x, lane = tid & 31, wid = tid >> 5;
    int tx = tid & 15, ty = tid >> 4;
    int node0 = blockIdx.x * 64;

    if (GATHER) {
        int day = *p_start + t;
        const int* rowptr = g_rowptr + (size_t)day * (NNODE + 1);
        const int* ecol = g_ecol + (size_t)day * NEDGE;
        const float* eval = g_eval + (size_t)day * NEDGE;
#pragma unroll
        for (int rr = 0; rr < 8; rr++) {
            int row = wid * 8 + rr;
            int node = node0 + row;
            float2 a = make_float2(0.f, 0.f);
            if (node < NNODE) {
                a = gather_row64(ecol, eval, rowptr[node], rowptr[node + 1], Asrc, 64, lane * 2);
                float2 bb = *reinterpret_cast<const float2*>(abias + lane * 2);
                a.x += bb.x;
                a.y += bb.y;
            }
            As[row * 68 + lane * 2] = a.x;
            As[row * 68 + lane * 2 + 1] = a.y;
        }
    } else {
        for (int idx = tid; idx < 64 * 16; idx += 256) {
            int row = idx >> 4, kk = (idx & 15) << 2;
            int node = node0 + row;
            float4 a = make_float4(0.f, 0.f, 0.f, 0.f);
            if (node < NNODE) a = *reinterpret_cast<const float4*>(Asrc + (size_t)node * 64 + kk);
            *reinterpret_cast<float4*>(&As[row * 68 + kk]) = a;
        }
    }

#pragma unroll 1
    for (int mc = 0; mc < 3; mc++) {
        __syncthreads();  // As ready (mc=0) / Bs consumers done (mc>0)
        for (int idx = tid; idx < 64 * 16; idx += 256) {
            int k = idx >> 4, mm = (idx & 15) << 2;
            *reinterpret_cast<float4*>(&Bs[k * 64 + mm]) =
                *reinterpret_cast<const float4*>(Bt + (size_t)k * 192 + mc * 64 + mm);
        }
        __syncthreads();
        float acc[4][4];
#pragma unroll
        for (int i = 0; i < 4; i++)
#pragma unroll
            for (int j = 0; j < 4; j++) acc[i][j] = 0.0f;
#pragma unroll 8
        for (int k = 0; k < 64; k++) {
            float4 b = *reinterpret_cast<const float4*>(&Bs[k * 64 + tx * 4]);
            float a0 = As[(ty * 4 + 0) * 68 + k];
            float a1 = As[(ty * 4 + 1) * 68 + k];
            float a2 = As[(ty * 4 + 2) * 68 + k];
            float a3 = As[(ty * 4 + 3) * 68 + k];
            acc[0][0] += a0 * b.x; acc[0][1] += a0 * b.y; acc[0][2] += a0 * b.z; acc[0][3] += a0 * b.w;
            acc[1][0] += a1 * b.x; acc[1][1] += a1 * b.y; acc[1][2] += a1 * b.z; acc[1][3] += a1 * b.w;
            acc[2][0] += a2 * b.x; acc[2][1] += a2 * b.y; acc[2][2] += a2 * b.z; acc[2][3] += a2 * b.w;
            acc[3][0] += a3 * b.x; acc[3][1] += a3 * b.y; acc[3][2] += a3 * b.z; acc[3][3] += a3 * b.w;
        }
        float4 ob = *reinterpret_cast<const float4*>(obias + mc * 64 + tx * 4);
#pragma unroll
        for (int i = 0; i < 4; i++) {
            int node = node0 + ty * 4 + i;
            if (node < NNODE) {
                float4 o;
                o.x = acc[i][0] + ob.x;
                o.y = acc[i][1] + ob.y;
                o.z = acc[i][2] + ob.z;
                o.w = acc[i][3] + ob.w;
                *reinterpret_cast<float4*>(out + (size_t)node * 192 + mc * 64 + tx * 4) = o;
            }
        }
    }
}

// ---------------- plain tiled GEMM for the node-predictor head ----------------
__global__ void np_gemm_kernel(const float* __restrict__ A, const float* __restrict__ B,
                               const float* __restrict__ obias, float* __restrict__ C) {
    __shared__ float As[64 * 68];
    __shared__ float Bs[64 * 64];
    const int tid = threadIdx.x;
    const int node0 = blockIdx.x * 64;
    const int tx = tid & 15, ty = tid >> 4;

    float acc[4][4];
#pragma unroll
    for (int i = 0; i < 4; i++)
#pragma unroll
        for (int j = 0; j < 4; j++) acc[i][j] = 0.0f;

    for (int kc = 0; kc < 128; kc += 64) {
        if (kc) __syncthreads();
        for (int idx = tid; idx < 64 * 16; idx += 256) {
            int row = idx >> 4, kk = (idx & 15) << 2;
            int node = node0 + row;
            float4 a = make_float4(0.f, 0.f, 0.f, 0.f);
            if (node < NNODE) a = *reinterpret_cast<const float4*>(A + (size_t)node * 128 + kc + kk);
            *reinterpret_cast<float4*>(&As[row * 68 + kk]) = a;
        }
        for (int idx = tid; idx < 64 * 16; idx += 256) {
            int k = idx >> 4, mm = (idx & 15) << 2;
            *reinterpret_cast<float4*>(&Bs[k * 64 + mm]) =
                *reinterpret_cast<const float4*>(B + (size_t)(kc + k) * 64 + mm);
        }
        __syncthreads();
#pragma unroll 8
        for (int k = 0; k < 64; k++) {
            float4 b = *reinterpret_cast<const float4*>(&Bs[k * 64 + tx * 4]);
            float a0 = As[(ty * 4 + 0) * 68 + k];
            float a1 = As[(ty * 4 + 1) * 68 + k];
            float a2 = As[(ty * 4 + 2) * 68 + k];
            float a3 = As[(ty * 4 + 3) * 68 + k];
            acc[0][0] += a0 * b.x; acc[0][1] += a0 * b.y; acc[0][2] += a0 * b.z; acc[0][3] += a0 * b.w;
            acc[1][0] += a1 * b.x; acc[1][1] += a1 * b.y; acc[1][2] += a1 * b.z; acc[1][3] += a1 * b.w;
            acc[2][0] += a2 * b.x; acc[2][1] += a2 * b.y; acc[2][2] += a2 * b.z; acc[2][3] += a2 * b.w;
            acc[3][0] += a3 * b.x; acc[3][1] += a3 * b.y; acc[3][2] += a3 * b.z; acc[3][3] += a3 * b.w;
        }
    }
#pragma unroll
    for (int i = 0; i < 4; i++) {
        int node = node0 + ty * 4 + i;
        if (node < NNODE) {
            float4 ob = *reinterpret_cast<const float4*>(obias + tx * 4);
            float4 o;
            o.x = fmaxf(acc[i][0] + ob.x, 0.f);
            o.y = fmaxf(acc[i][1] + ob.y, 0.f);
            o.z = fmaxf(acc[i][2] + ob.z, 0.f);
            o.w = fmaxf(acc[i][3] + ob.w, 0.f);
            *reinterpret_cast<float4*>(C + (size_t)node * 64 + tx * 4) = o;
        }
    }
}

// ---------------- GRU gate fuse ----------------
__global__ void gru_gate_kernel() {
    int idx = blockIdx.x * 256 + threadIdx.x;
    if (idx >= NNODE * 64) return;
    int n = idx >> 6;
    int j = idx & 63;
    const float* gi = g_gi + (size_t)n * 192;
    const float* gh = g_gh + (size_t)n * 192;
    float ir = gi[j], iz = gi[64 + j], in_ = gi[128 + j];
    float hr = gh[j], hz = gh[64 + j], hn = gh[128 + j];
    float r = sigmoidf_(ir + hr);
    float z = sigmoidf_(iz + hz);
    float nn = tanhf(in_ + r * hn);
    float hp = g_h[idx];
    g_h[idx] = (1.0f - z) * nn + z * hp;
}

// ---------------- batch norm ----------------
__global__ void bn_stats_kernel() {
    int col = threadIdx.x & 63;
    int rep = threadIdx.x >> 6;  // 0..3
    float s = 0.f, s2 = 0.f;
    for (int r = blockIdx.x * 4 + rep; r < NNODE; r += gridDim.x * 4) {
        float v = g_h[(size_t)r * 64 + col];
        s += v;
        s2 += v * v;
    }
    __shared__ float ss[4][64];
    __shared__ float ss2[4][64];
    ss[rep][col] = s;
    ss2[rep][col] = s2;
    __syncthreads();
    if (rep == 0) {
        s = ss[0][col] + ss[1][col] + ss[2][col] + ss[3][col];
        s2 = ss2[0][col] + ss2[1][col] + ss2[2][col] + ss2[3][col];
        atomicAdd(&g_stats[col], s);
        atomicAdd(&g_stats[64 + col], s2);
    }
}

__global__ void bn_norm_kernel(const float* __restrict__ gamma, const float* __restrict__ beta) {
    int idx = blockIdx.x * 256 + threadIdx.x;
    if (idx >= NNODE * 64) return;
    int n = idx >> 6;
    int col = idx & 63;
    float mean = g_stats[col] * (1.0f / NNODE);
    float var = g_stats[64 + col] * (1.0f / NNODE) - mean * mean;
    float inv = rsqrtf(var + 1e-5f);
    float v = (g_h[idx] - mean) * inv * gamma[col] + beta[col];
    g_z[(size_t)n * 128 + col] = v;
}

// ---------------- attention on day end_day+1 ----------------
__global__ void deg_kernel(const int* __restrict__ adj_idx, const int* __restrict__ end_day) {
    int e = blockIdx.x * 256 + threadIdx.x;
    if (e >= NEDGE) return;
    int day = *end_day + 1;
    const int* rowp = adj_idx + (size_t)day * 2 * NEDGE;
    int r = rowp[e];
    int c = rowp[NEDGE + e];
    if (r != c) atomicAdd(&g_deg[r], 1.0f);
}

__global__ void attn_kernel(const int* __restrict__ adj_idx, const int* __restrict__ end_day,
                            const float* __restrict__ aw, const float* __restrict__ ab) {
    int gid = blockIdx.x * 256 + threadIdx.x;
    int e = gid >> 5;
    if (e >= NEDGE) return;
    int lane = gid & 31;
    int day = *end_day + 1;
    const int* rowp = adj_idx + (size_t)day * 2 * NEDGE;
    int r = rowp[e];
    int c = rowp[NEDGE + e];
    if (r == c) return;
    const float* zr = g_z + (size_t)r * 128;
    const float* zc = g_z + (size_t)c * 128;
    float ec0 = zc[lane];
    float ec1 = zc[lane + 32];
    float p = zr[lane] * aw[lane] + zr[lane + 32] * aw[lane + 32] +
              ec0 * aw[64 + lane] + ec1 * aw[96 + lane];
#pragma unroll
    for (int o = 16; o > 0; o >>= 1) p += __shfl_xor_sync(0xffffffffu, p, o);
    float w = sigmoidf_(p + ab[0]);
    float d = g_deg[r];
    float invd = (d != 0.0f) ? (1.0f / d) : 1.0f;
    float ev = invd * w;
    atomicAdd(&g_z[(size_t)r * 128 + 64 + lane], ev * ec0);
    atomicAdd(&g_z[(size_t)r * 128 + 96 + lane], ev * ec1);
}

// ---------------- final logits + log_softmax ----------------
__global__ void logits_kernel(const float* __restrict__ w2, const float* __restrict__ b2,
                              float* __restrict__ out) {
    int gid = blockIdx.x * 256 + threadIdx.x;
    int n = gid >> 5;
    if (n >= NNODE) return;
    int lane = gid & 31;
    float v0 = g_x2[(size_t)n * 64 + lane];  // g_x2 holds h1 here
    float v1 = g_x2[(size_t)n * 64 + 32 + lane];
    float l0 = v0 * w2[lane * 2 + 0] + v1 * w2[(lane + 32) * 2 + 0];
    float l1 = v0 * w2[lane * 2 + 1] + v1 * w2[(lane + 32) * 2 + 1];
#pragma unroll
    for (int o = 16; o > 0; o >>= 1) {
        l0 += __shfl_down_sync(0xffffffffu, l0, o);
        l1 += __shfl_down_sync(0xffffffffu, l1, o);
    }
    if (lane == 0) {
        l0 += b2[0];
        l1 += b2[1];
        float m = fmaxf(l0, l1);
        float lse = m + logf(expf(l0 - m) + expf(l1 - m));
        out[(size_t)n * 2 + 0] = l0 - lse;
        out[(size_t)n * 2 + 1] = l1 - lse;
    }
}

// ---------------- host launch ----------------
extern "C" void kernel_launch(void* const* d_in, const int* in_sizes, int n_in,
                              void* d_out, int out_size) {
    const int* adj_idx = (const int*)d_in[0];
    const float* adj_val = (const float*)d_in[1];
    const int* p_start = (const int*)d_in[2];
    const int* p_end = (const int*)d_in[3];
    const float* W1 = (const float*)d_in[4];
    const float* b1 = (const float*)d_in[5];
    const float* W2 = (const float*)d_in[6];
    const float* b2 = (const float*)d_in[7];
    const float* w_ih = (const float*)d_in[8];
    const float* w_hh = (const float*)d_in[9];
    const float* b_ih = (const float*)d_in[10];
    const float* b_hh = (const float*)d_in[11];
    const float* bn_gamma = (const float*)d_in[12];
    const float* bn_beta = (const float*)d_in[13];
    const float* attn_w = (const float*)d_in[14];
    const float* attn_b = (const float*)d_in[15];
    const float* np_w1 = (const float*)d_in[16];
    const float* np_b1 = (const float*)d_in[17];
    const float* np_w2 = (const float*)d_in[18];
    const float* np_b2 = (const float*)d_in[19];
    float* out = (float*)d_out;

    float *x2, *h, *gi, *gh, *z, *deg, *stats, *wih_t, *whh_t;
    int* cnt;
    cudaGetSymbolAddress((void**)&x2, g_x2);
    cudaGetSymbolAddress((void**)&h, g_h);
    cudaGetSymbolAddress((void**)&gi, g_gi);
    cudaGetSymbolAddress((void**)&gh, g_gh);
    cudaGetSymbolAddress((void**)&z, g_z);
    cudaGetSymbolAddress((void**)&deg, g_deg);
    cudaGetSymbolAddress((void**)&stats, g_stats);
    cudaGetSymbolAddress((void**)&wih_t, g_wih_t);
    cudaGetSymbolAddress((void**)&whh_t, g_whh_t);
    cudaGetSymbolAddress((void**)&cnt, g_cnt);

    const int nGemmBlocks = (NNODE + 63) / 64;  // 782

    // ---- CSR build (all 8 days) ----
    zero_i_kernel<<<(SDAYS * NNODE + 255) / 256, 256>>>(cnt, SDAYS * NNODE);
    csr_count_kernel<<<(SDAYS * NEDGE + 255) / 256, 256>>>(adj_idx);
    csr_scan_block_kernel<<<dim3(BPD, SDAYS), 256>>>();
    csr_scan_part_kernel<<<SDAYS, 128>>>();
    csr_apply_kernel<<<(SDAYS * NNODE + 255) / 256, 256>>>();
    csr_scatter_kernel<<<(SDAYS * NEDGE + 255) / 256, 256>>>(adj_idx, adj_val);

    // ---- one-time prep ----
    transpose_w_kernel<<<(192 * 64 + 255) / 256, 256>>>(w_ih, wih_t);
    transpose_w_kernel<<<(192 * 64 + 255) / 256, 256>>>(w_hh, whh_t);
    zero_f_kernel<<<(NNODE * 64 + 255) / 256, 256>>>(h, NNODE * 64);
    zero_f_kernel<<<(NNODE * 128 + 255) / 256, 256>>>(z, NNODE * 128);
    zero_f_kernel<<<(NNODE + 255) / 256, 256>>>(deg, NNODE);
    zero_f_kernel<<<1, 128>>>(stats, 128);

    // ---- 7 GCN-GRU steps ----
    for (int t = 0; t < 7; t++) {
        gcn1_kernel<<<nGemmBlocks, 256>>>(p_start, t, W1, b1, W2);
        gru_gemm_kernel<true><<<nGemmBlocks, 256>>>(p_start, t, x2, b2, wih_t, b_ih, gi);
        gru_gemm_kernel<false><<<nGemmBlocks, 256>>>(p_start, t, h, nullptr, whh_t, b_hh, gh);
        gru_gate_kernel<<<(NNODE * 64 + 255) / 256, 256>>>();
    }

    // ---- batch norm -> z[:, 0:64] ----
    bn_stats_kernel<<<128, 256>>>();
    bn_norm_kernel<<<(NNODE * 64 + 255) / 256, 256>>>(bn_gamma, bn_beta);

    // ---- attention on day end_day+1 -> z[:, 64:128] ----
    deg_kernel<<<(NEDGE + 255) / 256, 256>>>(adj_idx, p_end);
    attn_kernel<<<(NEDGE * 32 + 255) / 256, 256>>>(adj_idx, p_end, attn_w, attn_b);

    // ---- node predictor head ----
    np_gemm_kernel<<<nGemmBlocks, 256>>>(z, np_w1, np_b1, x2);
    logits_kernel<<<(NNODE * 32 + 255) / 256, 256>>>(np_w2, np_b2, out);
}